// round 1
// baseline (speedup 1.0000x reference)
#include <cuda_runtime.h>

#define NN 100000
#define EMAX 1600000

// ---- scratch (device globals; no runtime allocation allowed) ----
__device__ int   g_deg[NN];
__device__ int   g_off[NN + 1];
__device__ int   g_cur[NN];
__device__ int   g_csr[EMAX + NN];      // src node per CSR slot (sorted by dst)
__device__ float g_h [NN * 64];         // transformed features for current layer
__device__ float g_fa[NN * 64];         // ping
__device__ float g_fb[NN * 64];         // pong
__device__ float g_es[NN * 4];          // per-node source attention logits
__device__ float g_ed[NN * 4];          // per-node dest attention logits

// ------------------------------------------------------------------
// CSR construction
// ------------------------------------------------------------------
__global__ void k_init_deg() {
    int i = blockIdx.x * blockDim.x + threadIdx.x;
    if (i < NN) g_deg[i] = 1;   // self-loop
}

__global__ void k_hist(const int* __restrict__ dst, int E) {
    int i = blockIdx.x * blockDim.x + threadIdx.x;
    if (i < E) atomicAdd(&g_deg[dst[i]], 1);
}

// single-block exclusive scan over g_deg -> g_off, g_cur
__global__ void k_scan() {
    __shared__ int sums[1024];
    const int CH = (NN + 1023) / 1024;
    int t = threadIdx.x;
    int lo = t * CH;
    int hi = lo + CH; if (hi > NN) hi = NN;
    int s = 0;
    for (int i = lo; i < hi; i++) s += g_deg[i];
    sums[t] = s;
    __syncthreads();
    for (int off = 1; off < 1024; off <<= 1) {
        int v = (t >= off) ? sums[t - off] : 0;
        __syncthreads();
        sums[t] += v;
        __syncthreads();
    }
    int pref = (t == 0) ? 0 : sums[t - 1];
    for (int i = lo; i < hi; i++) {
        g_off[i] = pref;
        g_cur[i] = pref;
        pref += g_deg[i];
    }
    if (t == 1023) g_off[NN] = sums[1023];
}

__global__ void k_fill(const int* __restrict__ src, const int* __restrict__ dst, int E) {
    int i = blockIdx.x * blockDim.x + threadIdx.x;
    int tot = E + NN;
    if (i >= tot) return;
    int s, d;
    if (i < E) { s = src[i]; d = dst[i]; }
    else       { s = i - E; d = s; }    // self-loops
    int p = atomicAdd(&g_cur[d], 1);
    g_csr[p] = s;
}

// ------------------------------------------------------------------
// Node transform: h = xin @ W ; es/ed = per-head attention dot products
// xin_sel: 0 -> external ptr (layer 0 input x, Fin=1), 1 -> g_fa, 2 -> g_fb
// ------------------------------------------------------------------
__global__ __launch_bounds__(256) void k_transform(
    const float* __restrict__ xext, int xin_sel, int Fin,
    const float* __restrict__ Wg,
    const float* __restrict__ avs,
    const float* __restrict__ avd)
{
    __shared__ float Ws[64 * 64];
    __shared__ float As[64], Ad[64];
    const float* xin = (xin_sel == 0) ? xext : (xin_sel == 1 ? g_fa : g_fb);
    int t = threadIdx.x;
    for (int i = t; i < Fin * 64; i += blockDim.x) Ws[i] = Wg[i];
    if (t < 64) { As[t] = avs[t]; Ad[t] = avd[t]; }
    __syncthreads();

    int lane = t & 31;
    int c0   = lane * 2;
    int wpg  = (gridDim.x * blockDim.x) >> 5;
    for (int n = (blockIdx.x * blockDim.x + t) >> 5; n < NN; n += wpg) {
        float a0, a1;
        if (Fin == 1) {
            float xv = xin[n];
            a0 = xv * Ws[c0];
            a1 = xv * Ws[c0 + 1];
        } else {
            a0 = 0.f; a1 = 0.f;
            const float* xr = xin + (size_t)n * 64;
            #pragma unroll
            for (int k = 0; k < 64; k += 4) {
                float4 xv = *(const float4*)(xr + k);
                float2 w0 = *(const float2*)(Ws + (k + 0) * 64 + c0);
                float2 w1 = *(const float2*)(Ws + (k + 1) * 64 + c0);
                float2 w2 = *(const float2*)(Ws + (k + 2) * 64 + c0);
                float2 w3 = *(const float2*)(Ws + (k + 3) * 64 + c0);
                a0 += xv.x * w0.x; a1 += xv.x * w0.y;
                a0 += xv.y * w1.x; a1 += xv.y * w1.y;
                a0 += xv.z * w2.x; a1 += xv.z * w2.y;
                a0 += xv.w * w3.x; a1 += xv.w * w3.y;
            }
        }
        size_t base = (size_t)n * 64 + c0;
        g_h[base]     = a0;
        g_h[base + 1] = a1;
        // per-head attention dots: lanes 8h..8h+7 own channels 16h..16h+15
        float ps = a0 * As[c0] + a1 * As[c0 + 1];
        float pd = a0 * Ad[c0] + a1 * Ad[c0 + 1];
        #pragma unroll
        for (int o = 4; o >= 1; o >>= 1) {
            ps += __shfl_down_sync(0xffffffffu, ps, o);
            pd += __shfl_down_sync(0xffffffffu, pd, o);
        }
        if ((lane & 7) == 0) {
            int hd = lane >> 3;
            g_es[n * 4 + hd] = ps;
            g_ed[n * 4 + hd] = pd;
        }
    }
}

// ------------------------------------------------------------------
// Edge aggregation: one warp per dst node, single-pass online softmax.
// out_sel: 1 -> g_fa, 2 -> g_fb
// ------------------------------------------------------------------
__global__ __launch_bounds__(256) void k_aggregate(
    const float* __restrict__ bias, int out_sel)
{
    float* xout = (out_sel == 1) ? g_fa : g_fb;
    int t    = threadIdx.x;
    int lane = t & 31;
    int c0   = lane * 2;
    int hd   = lane >> 3;
    float2 bv = *(const float2*)(bias + c0);
    int wpg = (gridDim.x * blockDim.x) >> 5;
    for (int n = (blockIdx.x * blockDim.x + t) >> 5; n < NN; n += wpg) {
        int beg = g_off[n], end = g_off[n + 1];
        float edv = g_ed[n * 4 + hd];
        float m = -1e30f, s = 0.f, acc0 = 0.f, acc1 = 0.f;
        for (int p = beg; p < end; p++) {
            int sc = g_csr[p];
            float e = g_es[sc * 4 + hd] + edv;
            e = (e > 0.f) ? e : 0.2f * e;           // leaky_relu(0.2)
            if (e > m) {                             // online softmax rescale
                float r = __expf(m - e);
                s *= r; acc0 *= r; acc1 *= r;
                m = e;
            }
            float w = __expf(e - m);
            float2 hv = *(const float2*)(g_h + (size_t)sc * 64 + c0);
            s    += w;
            acc0 += w * hv.x;
            acc1 += w * hv.y;
        }
        float inv = 1.f / (s + 1e-16f);
        size_t base = (size_t)n * 64 + c0;
        xout[base]     = acc0 * inv + bv.x;
        xout[base + 1] = acc1 * inv + bv.y;
    }
}

// ------------------------------------------------------------------
// Fused MLP + decoder + softmax: reads g_fa, writes out[N,4]
// ------------------------------------------------------------------
__global__ __launch_bounds__(256) void k_mlp(
    const float* __restrict__ lw1, const float* __restrict__ lb1,
    const float* __restrict__ lw2, const float* __restrict__ lb2,
    const float* __restrict__ dw,  const float* __restrict__ db,
    float* __restrict__ out)
{
    __shared__ float W1s[64 * 64];
    __shared__ float W2s[64 * 16];
    __shared__ float b1s[64], b2s[16], dws[64], dbs[4];
    __shared__ float t1s[8][64];
    __shared__ float t2s[8][16];
    __shared__ float lgs[8][4];
    int t = threadIdx.x;
    for (int i = t; i < 64 * 64; i += blockDim.x) W1s[i] = lw1[i];
    for (int i = t; i < 64 * 16; i += blockDim.x) W2s[i] = lw2[i];
    if (t < 64) b1s[t] = lb1[t];
    if (t < 16) b2s[t] = lb2[t];
    if (t < 64) dws[t] = dw[t];
    if (t < 4)  dbs[t] = db[t];
    __syncthreads();

    int lane = t & 31, w = t >> 5;
    int c0 = lane * 2;
    int wpg = (gridDim.x * blockDim.x) >> 5;
    for (int n = (blockIdx.x * blockDim.x + t) >> 5; n < NN; n += wpg) {
        const float* xr = g_fa + (size_t)n * 64;
        float a0 = b1s[c0], a1 = b1s[c0 + 1];
        #pragma unroll
        for (int k = 0; k < 64; k += 4) {
            float4 xv = *(const float4*)(xr + k);
            float2 w0 = *(const float2*)(W1s + (k + 0) * 64 + c0);
            float2 w1 = *(const float2*)(W1s + (k + 1) * 64 + c0);
            float2 w2 = *(const float2*)(W1s + (k + 2) * 64 + c0);
            float2 w3 = *(const float2*)(W1s + (k + 3) * 64 + c0);
            a0 += xv.x * w0.x; a1 += xv.x * w0.y;
            a0 += xv.y * w1.x; a1 += xv.y * w1.y;
            a0 += xv.z * w2.x; a1 += xv.z * w2.y;
            a0 += xv.w * w3.x; a1 += xv.w * w3.y;
        }
        a0 = a0 > 0.f ? a0 : 0.f;
        a1 = a1 > 0.f ? a1 : 0.f;
        t1s[w][c0]     = a0;
        t1s[w][c0 + 1] = a1;
        __syncwarp();
        if (lane < 16) {
            float acc = b2s[lane];
            #pragma unroll
            for (int k = 0; k < 64; k++) acc += t1s[w][k] * W2s[k * 16 + lane];
            t2s[w][lane] = acc;
        }
        __syncwarp();
        if (lane < 4) {
            float lg = dbs[lane];
            #pragma unroll
            for (int i = 0; i < 16; i++) lg += t2s[w][i] * dws[i * 4 + lane];
            lgs[w][lane] = lg;
        }
        __syncwarp();
        if (lane < 4) {
            float l0 = lgs[w][0], l1 = lgs[w][1], l2 = lgs[w][2], l3 = lgs[w][3];
            float mx = fmaxf(fmaxf(l0, l1), fmaxf(l2, l3));
            float e0 = __expf(l0 - mx), e1 = __expf(l1 - mx);
            float e2 = __expf(l2 - mx), e3 = __expf(l3 - mx);
            float den = e0 + e1 + e2 + e3;
            float mine = (lane == 0) ? e0 : (lane == 1) ? e1 : (lane == 2) ? e2 : e3;
            out[(size_t)n * 4 + lane] = mine / den;
        }
        __syncwarp();
    }
}

// ------------------------------------------------------------------
extern "C" void kernel_launch(void* const* d_in, const int* in_sizes, int n_in,
                              void* d_out, int out_size)
{
    const float* x   = (const float*)d_in[0];
    const int*   ei  = (const int*)  d_in[1];
    int E = in_sizes[1] / 2;
    const int* src = ei;
    const int* dst = ei + E;
    const float* W0  = (const float*)d_in[2];
    const float* as0 = (const float*)d_in[3];
    const float* ad0 = (const float*)d_in[4];
    const float* b0  = (const float*)d_in[5];
    const float* W1  = (const float*)d_in[6];
    const float* as1 = (const float*)d_in[7];
    const float* ad1 = (const float*)d_in[8];
    const float* b1  = (const float*)d_in[9];
    const float* W2  = (const float*)d_in[10];
    const float* as2 = (const float*)d_in[11];
    const float* ad2 = (const float*)d_in[12];
    const float* b2  = (const float*)d_in[13];
    const float* lw1 = (const float*)d_in[14];
    const float* lb1 = (const float*)d_in[15];
    const float* lw2 = (const float*)d_in[16];
    const float* lb2 = (const float*)d_in[17];
    const float* dw  = (const float*)d_in[18];
    const float* db  = (const float*)d_in[19];
    float* out = (float*)d_out;

    const int NB = 1216;   // 152 SMs * 8 blocks
    const int NT = 256;

    // CSR build (reused across all 3 GAT layers)
    k_init_deg<<<(NN + 255) / 256, 256>>>();
    k_hist<<<(E + 255) / 256, 256>>>(dst, E);
    k_scan<<<1, 1024>>>();
    k_fill<<<(E + NN + 255) / 256, 256>>>(src, dst, E);

    // GAT layer 0 (Fin=1): out -> g_fa
    k_transform<<<NB, NT>>>(x, 0, 1, W0, as0, ad0);
    k_aggregate<<<NB, NT>>>(b0, 1);
    // GAT layer 1 (Fin=64): in g_fa, out -> g_fb
    k_transform<<<NB, NT>>>(nullptr, 1, 64, W1, as1, ad1);
    k_aggregate<<<NB, NT>>>(b1, 2);
    // GAT layer 2 (Fin=64): in g_fb, out -> g_fa
    k_transform<<<NB, NT>>>(nullptr, 2, 64, W2, as2, ad2);
    k_aggregate<<<NB, NT>>>(b2, 1);
    // MLP + decoder + softmax: reads g_fa
    k_mlp<<<NB, NT>>>(lw1, lb1, lw2, lb2, dw, db, out);
}

// round 2
// speedup vs baseline: 1.0459x; 1.0459x over previous
#include <cuda_runtime.h>

#define NN 100000
#define EMAX 1600000

// ---- scratch (device globals; no runtime allocation allowed) ----
__device__ int   g_deg[NN];
__device__ int   g_off[NN + 1];
__device__ int   g_cur[NN];
__device__ int   g_csr[EMAX + NN];      // src node per CSR slot (sorted by dst)
__device__ float g_h [NN * 64];         // transformed features for current layer
__device__ float g_fa[NN * 64];         // ping
__device__ float g_fb[NN * 64];         // pong
__device__ float g_es[NN * 4];          // per-node source attention logits
__device__ float g_ed[NN * 4];          // per-node dest attention logits

// ------------------------------------------------------------------
// CSR construction
// ------------------------------------------------------------------
__global__ void k_init_deg() {
    int i = blockIdx.x * blockDim.x + threadIdx.x;
    if (i < NN) g_deg[i] = 1;   // self-loop
}

__global__ void k_hist(const int* __restrict__ dst, int E) {
    int i = blockIdx.x * blockDim.x + threadIdx.x;
    if (i < E) atomicAdd(&g_deg[dst[i]], 1);
}

// single-block exclusive scan over g_deg -> g_off, g_cur
__global__ void k_scan() {
    __shared__ int sums[1024];
    const int CH = (NN + 1023) / 1024;
    int t = threadIdx.x;
    int lo = t * CH;
    int hi = lo + CH; if (hi > NN) hi = NN;
    int s = 0;
    for (int i = lo; i < hi; i++) s += g_deg[i];
    sums[t] = s;
    __syncthreads();
    for (int off = 1; off < 1024; off <<= 1) {
        int v = (t >= off) ? sums[t - off] : 0;
        __syncthreads();
        sums[t] += v;
        __syncthreads();
    }
    int pref = (t == 0) ? 0 : sums[t - 1];
    for (int i = lo; i < hi; i++) {
        g_off[i] = pref;
        g_cur[i] = pref;
        pref += g_deg[i];
    }
    if (t == 1023) g_off[NN] = sums[1023];
}

__global__ void k_fill(const int* __restrict__ src, const int* __restrict__ dst, int E) {
    int i = blockIdx.x * blockDim.x + threadIdx.x;
    int tot = E + NN;
    if (i >= tot) return;
    int s, d;
    if (i < E) { s = src[i]; d = dst[i]; }
    else       { s = i - E; d = s; }    // self-loops
    int p = atomicAdd(&g_cur[d], 1);
    g_csr[p] = s;
}

// ------------------------------------------------------------------
// Node transform: h = xin @ W ; es/ed = per-head attention dot products
// xin_sel: 0 -> external ptr (layer 0 input x, Fin=1), 1 -> g_fa, 2 -> g_fb
// One warp per node.
// ------------------------------------------------------------------
__global__ __launch_bounds__(256) void k_transform(
    const float* __restrict__ xext, int xin_sel, int Fin,
    const float* __restrict__ Wg,
    const float* __restrict__ avs,
    const float* __restrict__ avd)
{
    __shared__ float Ws[64 * 64];
    __shared__ float As[64], Ad[64];
    const float* xin = (xin_sel == 0) ? xext : (xin_sel == 1 ? g_fa : g_fb);
    int t = threadIdx.x;
    for (int i = t; i < Fin * 64; i += blockDim.x) Ws[i] = Wg[i];
    if (t < 64) { As[t] = avs[t]; Ad[t] = avd[t]; }
    __syncthreads();

    int lane = t & 31;
    int c0   = lane * 2;
    int n = blockIdx.x * 8 + (t >> 5);
    if (n >= NN) return;

    float a0, a1;
    if (Fin == 1) {
        float xv = __ldg(xin + n);
        a0 = xv * Ws[c0];
        a1 = xv * Ws[c0 + 1];
    } else {
        a0 = 0.f; a1 = 0.f;
        const float* xr = xin + (size_t)n * 64;
        #pragma unroll
        for (int k = 0; k < 64; k += 4) {
            float4 xv = __ldg((const float4*)(xr + k));
            float2 w0 = *(const float2*)(Ws + (k + 0) * 64 + c0);
            float2 w1 = *(const float2*)(Ws + (k + 1) * 64 + c0);
            float2 w2 = *(const float2*)(Ws + (k + 2) * 64 + c0);
            float2 w3 = *(const float2*)(Ws + (k + 3) * 64 + c0);
            a0 += xv.x * w0.x; a1 += xv.x * w0.y;
            a0 += xv.y * w1.x; a1 += xv.y * w1.y;
            a0 += xv.z * w2.x; a1 += xv.z * w2.y;
            a0 += xv.w * w3.x; a1 += xv.w * w3.y;
        }
    }
    size_t base = (size_t)n * 64 + c0;
    g_h[base]     = a0;
    g_h[base + 1] = a1;
    // per-head attention dots: lanes 8h..8h+7 own channels 16h..16h+15
    float ps = a0 * As[c0] + a1 * As[c0 + 1];
    float pd = a0 * Ad[c0] + a1 * Ad[c0 + 1];
    #pragma unroll
    for (int o = 4; o >= 1; o >>= 1) {
        ps += __shfl_down_sync(0xffffffffu, ps, o);
        pd += __shfl_down_sync(0xffffffffu, pd, o);
    }
    if ((lane & 7) == 0) {
        int hd = lane >> 3;
        g_es[n * 4 + hd] = ps;
        g_ed[n * 4 + hd] = pd;
    }
}

// ------------------------------------------------------------------
// Edge aggregation: one warp per dst node, branch-free two-pass softmax.
// Pass 1: max over edges (pure fmax chain, loads fully pipelineable)
// Pass 2: exp + weighted accumulate (loads independent across edges)
// ------------------------------------------------------------------
__device__ __forceinline__ float leaky02(float e) {
    return (e > 0.f) ? e : 0.2f * e;
}

__global__ __launch_bounds__(256) void k_aggregate(
    const float* __restrict__ bias, int out_sel)
{
    float* xout = (out_sel == 1) ? g_fa : g_fb;
    int t    = threadIdx.x;
    int lane = t & 31;
    int c0   = lane * 2;
    int hd   = lane >> 3;
    int n = blockIdx.x * 8 + (t >> 5);
    if (n >= NN) return;

    float2 bv = *(const float2*)(bias + c0);
    int beg = __ldg(&g_off[n]), end = __ldg(&g_off[n + 1]);
    float edv = __ldg(&g_ed[n * 4 + hd]);

    // ---- pass 1: max logit (branch-free, unrolled for MLP) ----
    float m = -1e30f;
    int p = beg;
    for (; p + 4 <= end; p += 4) {
        int s0 = __ldg(&g_csr[p]);
        int s1 = __ldg(&g_csr[p + 1]);
        int s2 = __ldg(&g_csr[p + 2]);
        int s3 = __ldg(&g_csr[p + 3]);
        float e0 = leaky02(__ldg(&g_es[s0 * 4 + hd]) + edv);
        float e1 = leaky02(__ldg(&g_es[s1 * 4 + hd]) + edv);
        float e2 = leaky02(__ldg(&g_es[s2 * 4 + hd]) + edv);
        float e3 = leaky02(__ldg(&g_es[s3 * 4 + hd]) + edv);
        m = fmaxf(m, fmaxf(fmaxf(e0, e1), fmaxf(e2, e3)));
    }
    for (; p < end; p++) {
        int sc = __ldg(&g_csr[p]);
        m = fmaxf(m, leaky02(__ldg(&g_es[sc * 4 + hd]) + edv));
    }

    // ---- pass 2: exp weights + accumulate ----
    float s = 0.f, acc0 = 0.f, acc1 = 0.f;
    p = beg;
    for (; p + 2 <= end; p += 2) {
        int s0 = __ldg(&g_csr[p]);
        int s1 = __ldg(&g_csr[p + 1]);
        float2 h0 = __ldg((const float2*)(g_h + (size_t)s0 * 64 + c0));
        float2 h1 = __ldg((const float2*)(g_h + (size_t)s1 * 64 + c0));
        float e0 = leaky02(__ldg(&g_es[s0 * 4 + hd]) + edv);
        float e1 = leaky02(__ldg(&g_es[s1 * 4 + hd]) + edv);
        float w0 = __expf(e0 - m);
        float w1 = __expf(e1 - m);
        s    += w0 + w1;
        acc0 += w0 * h0.x;
        acc1 += w0 * h0.y;
        acc0 += w1 * h1.x;
        acc1 += w1 * h1.y;
    }
    for (; p < end; p++) {
        int sc = __ldg(&g_csr[p]);
        float2 hv = __ldg((const float2*)(g_h + (size_t)sc * 64 + c0));
        float e = leaky02(__ldg(&g_es[sc * 4 + hd]) + edv);
        float w = __expf(e - m);
        s    += w;
        acc0 += w * hv.x;
        acc1 += w * hv.y;
    }

    float inv = 1.f / (s + 1e-16f);
    size_t base = (size_t)n * 64 + c0;
    xout[base]     = acc0 * inv + bv.x;
    xout[base + 1] = acc1 * inv + bv.y;
}

// ------------------------------------------------------------------
// Fused MLP + decoder + softmax: reads g_fa, writes out[N,4]
// One warp per node.
// ------------------------------------------------------------------
__global__ __launch_bounds__(256) void k_mlp(
    const float* __restrict__ lw1, const float* __restrict__ lb1,
    const float* __restrict__ lw2, const float* __restrict__ lb2,
    const float* __restrict__ dw,  const float* __restrict__ db,
    float* __restrict__ out)
{
    __shared__ float W1s[64 * 64];
    __shared__ float W2s[64 * 16];
    __shared__ float b1s[64], b2s[16], dws[64], dbs[4];
    __shared__ float t1s[8][64];
    __shared__ float t2s[8][16];
    __shared__ float lgs[8][4];
    int t = threadIdx.x;
    for (int i = t; i < 64 * 64; i += blockDim.x) W1s[i] = lw1[i];
    for (int i = t; i < 64 * 16; i += blockDim.x) W2s[i] = lw2[i];
    if (t < 64) b1s[t] = lb1[t];
    if (t < 16) b2s[t] = lb2[t];
    if (t < 64) dws[t] = dw[t];
    if (t < 4)  dbs[t] = db[t];
    __syncthreads();

    int lane = t & 31, w = t >> 5;
    int c0 = lane * 2;
    int n = blockIdx.x * 8 + w;
    if (n >= NN) return;

    const float* xr = g_fa + (size_t)n * 64;
    float a0 = b1s[c0], a1 = b1s[c0 + 1];
    #pragma unroll
    for (int k = 0; k < 64; k += 4) {
        float4 xv = __ldg((const float4*)(xr + k));
        float2 w0 = *(const float2*)(W1s + (k + 0) * 64 + c0);
        float2 w1 = *(const float2*)(W1s + (k + 1) * 64 + c0);
        float2 w2 = *(const float2*)(W1s + (k + 2) * 64 + c0);
        float2 w3 = *(const float2*)(W1s + (k + 3) * 64 + c0);
        a0 += xv.x * w0.x; a1 += xv.x * w0.y;
        a0 += xv.y * w1.x; a1 += xv.y * w1.y;
        a0 += xv.z * w2.x; a1 += xv.z * w2.y;
        a0 += xv.w * w3.x; a1 += xv.w * w3.y;
    }
    a0 = a0 > 0.f ? a0 : 0.f;
    a1 = a1 > 0.f ? a1 : 0.f;
    t1s[w][c0]     = a0;
    t1s[w][c0 + 1] = a1;
    __syncwarp();
    if (lane < 16) {
        float acc = b2s[lane];
        #pragma unroll
        for (int k = 0; k < 64; k++) acc += t1s[w][k] * W2s[k * 16 + lane];
        t2s[w][lane] = acc;
    }
    __syncwarp();
    if (lane < 4) {
        float lg = dbs[lane];
        #pragma unroll
        for (int i = 0; i < 16; i++) lg += t2s[w][i] * dws[i * 4 + lane];
        lgs[w][lane] = lg;
    }
    __syncwarp();
    if (lane < 4) {
        float l0 = lgs[w][0], l1 = lgs[w][1], l2 = lgs[w][2], l3 = lgs[w][3];
        float mx = fmaxf(fmaxf(l0, l1), fmaxf(l2, l3));
        float e0 = __expf(l0 - mx), e1 = __expf(l1 - mx);
        float e2 = __expf(l2 - mx), e3 = __expf(l3 - mx);
        float den = e0 + e1 + e2 + e3;
        float mine = (lane == 0) ? e0 : (lane == 1) ? e1 : (lane == 2) ? e2 : e3;
        out[(size_t)n * 4 + lane] = mine / den;
    }
}

// ------------------------------------------------------------------
extern "C" void kernel_launch(void* const* d_in, const int* in_sizes, int n_in,
                              void* d_out, int out_size)
{
    const float* x   = (const float*)d_in[0];
    const int*   ei  = (const int*)  d_in[1];
    int E = in_sizes[1] / 2;
    const int* src = ei;
    const int* dst = ei + E;
    const float* W0  = (const float*)d_in[2];
    const float* as0 = (const float*)d_in[3];
    const float* ad0 = (const float*)d_in[4];
    const float* b0  = (const float*)d_in[5];
    const float* W1  = (const float*)d_in[6];
    const float* as1 = (const float*)d_in[7];
    const float* ad1 = (const float*)d_in[8];
    const float* b1  = (const float*)d_in[9];
    const float* W2  = (const float*)d_in[10];
    const float* as2 = (const float*)d_in[11];
    const float* ad2 = (const float*)d_in[12];
    const float* b2  = (const float*)d_in[13];
    const float* lw1 = (const float*)d_in[14];
    const float* lb1 = (const float*)d_in[15];
    const float* lw2 = (const float*)d_in[16];
    const float* lb2 = (const float*)d_in[17];
    const float* dw  = (const float*)d_in[18];
    const float* db  = (const float*)d_in[19];
    float* out = (float*)d_out;

    const int NODE_BLOCKS = (NN + 7) / 8;   // one warp per node, 8 warps/block
    const int NT = 256;

    // CSR build (reused across all 3 GAT layers)
    k_init_deg<<<(NN + 255) / 256, 256>>>();
    k_hist<<<(E + 255) / 256, 256>>>(dst, E);
    k_scan<<<1, 1024>>>();
    k_fill<<<(E + NN + 255) / 256, 256>>>(src, dst, E);

    // GAT layer 0 (Fin=1): out -> g_fa
    k_transform<<<NODE_BLOCKS, NT>>>(x, 0, 1, W0, as0, ad0);
    k_aggregate<<<NODE_BLOCKS, NT>>>(b0, 1);
    // GAT layer 1 (Fin=64): in g_fa, out -> g_fb
    k_transform<<<NODE_BLOCKS, NT>>>(nullptr, 1, 64, W1, as1, ad1);
    k_aggregate<<<NODE_BLOCKS, NT>>>(b1, 2);
    // GAT layer 2 (Fin=64): in g_fb, out -> g_fa
    k_transform<<<NODE_BLOCKS, NT>>>(nullptr, 2, 64, W2, as2, ad2);
    k_aggregate<<<NODE_BLOCKS, NT>>>(b2, 1);
    // MLP + decoder + softmax: reads g_fa
    k_mlp<<<NODE_BLOCKS, NT>>>(lw1, lb1, lw2, lb2, dw, db, out);
}

// round 3
// speedup vs baseline: 1.1771x; 1.1254x over previous
#include <cuda_runtime.h>

#define NN 100000
#define EMAX 1600000

// ---- scratch (device globals; no runtime allocation allowed) ----
__device__ int      g_deg[NN];
__device__ int      g_off[NN + 1];
__device__ int      g_cur[NN];
__device__ int      g_csr[EMAX + NN];   // src node per CSR slot (sorted by dst)
__device__ float    g_h [NN * 64];      // transformed features for current layer
__device__ float    g_fa[NN * 64];      // ping
__device__ float    g_fb[NN * 64];      // pong
__device__ float    g_es[NN * 4];       // per-node source attention logits
__device__ float    g_ed[NN * 4];       // per-node dest attention logits
__device__ unsigned g_gmax[12];         // per-layer per-head global max of es (ordered-uint enc)

// ordered-uint encoding for float atomicMax
__device__ __forceinline__ unsigned fenc(float f) {
    unsigned u = __float_as_uint(f);
    return u ^ ((u & 0x80000000u) ? 0xFFFFFFFFu : 0x80000000u);
}
__device__ __forceinline__ float fdec(unsigned e) {
    unsigned u = e ^ ((e & 0x80000000u) ? 0x80000000u : 0xFFFFFFFFu);
    return __uint_as_float(u);
}
__device__ __forceinline__ float leaky02(float e) {
    return (e > 0.f) ? e : 0.2f * e;
}

// ------------------------------------------------------------------
// CSR construction
// ------------------------------------------------------------------
__global__ void k_init_deg() {
    int i = blockIdx.x * blockDim.x + threadIdx.x;
    if (i < NN) g_deg[i] = 1;           // self-loop
    if (i < 12) g_gmax[i] = 0u;         // -inf in ordered encoding
}

__global__ void k_hist(const int* __restrict__ dst, int E) {
    int i = blockIdx.x * blockDim.x + threadIdx.x;
    if (i < E) atomicAdd(&g_deg[dst[i]], 1);
}

// single-block exclusive scan over g_deg -> g_off, g_cur
__global__ void k_scan() {
    __shared__ int sums[1024];
    const int CH = (NN + 1023) / 1024;
    int t = threadIdx.x;
    int lo = t * CH;
    int hi = lo + CH; if (hi > NN) hi = NN;
    int s = 0;
    for (int i = lo; i < hi; i++) s += g_deg[i];
    sums[t] = s;
    __syncthreads();
    for (int off = 1; off < 1024; off <<= 1) {
        int v = (t >= off) ? sums[t - off] : 0;
        __syncthreads();
        sums[t] += v;
        __syncthreads();
    }
    int pref = (t == 0) ? 0 : sums[t - 1];
    for (int i = lo; i < hi; i++) {
        g_off[i] = pref;
        g_cur[i] = pref;
        pref += g_deg[i];
    }
    if (t == 1023) g_off[NN] = sums[1023];
}

__global__ void k_fill(const int* __restrict__ src, const int* __restrict__ dst, int E) {
    int i = blockIdx.x * blockDim.x + threadIdx.x;
    int tot = E + NN;
    if (i >= tot) return;
    int s, d;
    if (i < E) { s = src[i]; d = dst[i]; }
    else       { s = i - E; d = s; }    // self-loops
    int p = atomicAdd(&g_cur[d], 1);
    g_csr[p] = s;
}

// ------------------------------------------------------------------
// Node transform: h = xin @ W ; es/ed = per-head attention dot products
// One warp per node.
// ------------------------------------------------------------------
__global__ __launch_bounds__(256) void k_transform(
    const float* __restrict__ xext, int xin_sel, int Fin,
    const float* __restrict__ Wg,
    const float* __restrict__ avs,
    const float* __restrict__ avd)
{
    __shared__ float Ws[64 * 64];
    __shared__ float As[64], Ad[64];
    const float* xin = (xin_sel == 0) ? xext : (xin_sel == 1 ? g_fa : g_fb);
    int t = threadIdx.x;
    for (int i = t; i < Fin * 64; i += blockDim.x) Ws[i] = Wg[i];
    if (t < 64) { As[t] = avs[t]; Ad[t] = avd[t]; }
    __syncthreads();

    int lane = t & 31;
    int c0   = lane * 2;
    int n = blockIdx.x * 8 + (t >> 5);
    if (n >= NN) return;

    float a0, a1;
    if (Fin == 1) {
        float xv = __ldg(xin + n);
        a0 = xv * Ws[c0];
        a1 = xv * Ws[c0 + 1];
    } else {
        a0 = 0.f; a1 = 0.f;
        const float* xr = xin + (size_t)n * 64;
        #pragma unroll
        for (int k = 0; k < 64; k += 4) {
            float4 xv = __ldg((const float4*)(xr + k));
            float2 w0 = *(const float2*)(Ws + (k + 0) * 64 + c0);
            float2 w1 = *(const float2*)(Ws + (k + 1) * 64 + c0);
            float2 w2 = *(const float2*)(Ws + (k + 2) * 64 + c0);
            float2 w3 = *(const float2*)(Ws + (k + 3) * 64 + c0);
            a0 += xv.x * w0.x; a1 += xv.x * w0.y;
            a0 += xv.y * w1.x; a1 += xv.y * w1.y;
            a0 += xv.z * w2.x; a1 += xv.z * w2.y;
            a0 += xv.w * w3.x; a1 += xv.w * w3.y;
        }
    }
    size_t base = (size_t)n * 64 + c0;
    g_h[base]     = a0;
    g_h[base + 1] = a1;
    // per-head attention dots: lanes 8h..8h+7 own channels 16h..16h+15
    float ps = a0 * As[c0] + a1 * As[c0 + 1];
    float pd = a0 * Ad[c0] + a1 * Ad[c0 + 1];
    #pragma unroll
    for (int o = 4; o >= 1; o >>= 1) {
        ps += __shfl_down_sync(0xffffffffu, ps, o);
        pd += __shfl_down_sync(0xffffffffu, pd, o);
    }
    if ((lane & 7) == 0) {
        int hd = lane >> 3;
        g_es[n * 4 + hd] = ps;
        g_ed[n * 4 + hd] = pd;
    }
}

// ------------------------------------------------------------------
// Per-head global max of es (for safe single-pass softmax bound)
// ------------------------------------------------------------------
__global__ void k_gmax(int layer) {
    float m0 = -1e30f, m1 = -1e30f, m2 = -1e30f, m3 = -1e30f;
    for (int i = blockIdx.x * blockDim.x + threadIdx.x; i < NN;
         i += gridDim.x * blockDim.x) {
        float4 v = *(const float4*)(g_es + (size_t)i * 4);
        m0 = fmaxf(m0, v.x); m1 = fmaxf(m1, v.y);
        m2 = fmaxf(m2, v.z); m3 = fmaxf(m3, v.w);
    }
    #pragma unroll
    for (int o = 16; o >= 1; o >>= 1) {
        m0 = fmaxf(m0, __shfl_xor_sync(0xffffffffu, m0, o));
        m1 = fmaxf(m1, __shfl_xor_sync(0xffffffffu, m1, o));
        m2 = fmaxf(m2, __shfl_xor_sync(0xffffffffu, m2, o));
        m3 = fmaxf(m3, __shfl_xor_sync(0xffffffffu, m3, o));
    }
    if ((threadIdx.x & 31) == 0) {
        atomicMax(&g_gmax[layer * 4 + 0], fenc(m0));
        atomicMax(&g_gmax[layer * 4 + 1], fenc(m1));
        atomicMax(&g_gmax[layer * 4 + 2], fenc(m2));
        atomicMax(&g_gmax[layer * 4 + 3], fenc(m3));
    }
}

// ------------------------------------------------------------------
// Single-pass softmax aggregation core (one warp per node).
// Returns normalized, biased output pair for this lane's 2 channels.
// ------------------------------------------------------------------
__device__ __forceinline__ void agg_node(
    int n, int c0, int hd, int layer, const float* __restrict__ bias,
    float& o0, float& o1)
{
    int beg = __ldg(&g_off[n]), end = __ldg(&g_off[n + 1]);
    float edv = __ldg(&g_ed[n * 4 + hd]);
    float m = leaky02(fdec(g_gmax[layer * 4 + hd]) + edv);  // >= every edge logit

    float s = 0.f, acc0 = 0.f, acc1 = 0.f;
    int p = beg;
    for (; p + 4 <= end; p += 4) {
        int s0 = __ldg(&g_csr[p]);
        int s1 = __ldg(&g_csr[p + 1]);
        int s2 = __ldg(&g_csr[p + 2]);
        int s3 = __ldg(&g_csr[p + 3]);
        float  e0 = __ldg(&g_es[s0 * 4 + hd]);
        float  e1 = __ldg(&g_es[s1 * 4 + hd]);
        float  e2 = __ldg(&g_es[s2 * 4 + hd]);
        float  e3 = __ldg(&g_es[s3 * 4 + hd]);
        float2 h0 = __ldg((const float2*)(g_h + (size_t)s0 * 64 + c0));
        float2 h1 = __ldg((const float2*)(g_h + (size_t)s1 * 64 + c0));
        float2 h2 = __ldg((const float2*)(g_h + (size_t)s2 * 64 + c0));
        float2 h3 = __ldg((const float2*)(g_h + (size_t)s3 * 64 + c0));
        float w0 = __expf(leaky02(e0 + edv) - m);
        float w1 = __expf(leaky02(e1 + edv) - m);
        float w2 = __expf(leaky02(e2 + edv) - m);
        float w3 = __expf(leaky02(e3 + edv) - m);
        s    += (w0 + w1) + (w2 + w3);
        acc0 += w0 * h0.x; acc1 += w0 * h0.y;
        acc0 += w1 * h1.x; acc1 += w1 * h1.y;
        acc0 += w2 * h2.x; acc1 += w2 * h2.y;
        acc0 += w3 * h3.x; acc1 += w3 * h3.y;
    }
    for (; p < end; p++) {
        int sc = __ldg(&g_csr[p]);
        float  e  = __ldg(&g_es[sc * 4 + hd]);
        float2 hv = __ldg((const float2*)(g_h + (size_t)sc * 64 + c0));
        float w = __expf(leaky02(e + edv) - m);
        s    += w;
        acc0 += w * hv.x;
        acc1 += w * hv.y;
    }
    float inv = 1.f / (s + 1e-16f);
    o0 = acc0 * inv + bias[c0];
    o1 = acc1 * inv + bias[c0 + 1];
}

// ------------------------------------------------------------------
// Aggregation -> feature buffer (layers 0 and 1)
// ------------------------------------------------------------------
__global__ __launch_bounds__(256) void k_aggregate(
    const float* __restrict__ bias, int out_sel, int layer)
{
    float* xout = (out_sel == 1) ? g_fa : g_fb;
    int t    = threadIdx.x;
    int lane = t & 31;
    int c0   = lane * 2;
    int hd   = lane >> 3;
    int n = blockIdx.x * 8 + (t >> 5);
    if (n >= NN) return;
    float o0, o1;
    agg_node(n, c0, hd, layer, bias, o0, o1);
    size_t base = (size_t)n * 64 + c0;
    xout[base]     = o0;
    xout[base + 1] = o1;
}

// ------------------------------------------------------------------
// Aggregation (layer 2) fused with MLP + decoder + softmax epilogue
// ------------------------------------------------------------------
__global__ __launch_bounds__(256) void k_agg_mlp(
    const float* __restrict__ bias, int layer,
    const float* __restrict__ lw1, const float* __restrict__ lb1,
    const float* __restrict__ lw2, const float* __restrict__ lb2,
    const float* __restrict__ dw,  const float* __restrict__ db,
    float* __restrict__ out)
{
    __shared__ float W1s[64 * 64];
    __shared__ float W2s[64 * 16];
    __shared__ float b1s[64], b2s[16], dws[64], dbs[4];
    __shared__ float t1s[8][64];
    __shared__ float t2s[8][16];
    __shared__ float lgs[8][4];
    int t = threadIdx.x;
    for (int i = t; i < 64 * 64; i += blockDim.x) W1s[i] = lw1[i];
    for (int i = t; i < 64 * 16; i += blockDim.x) W2s[i] = lw2[i];
    if (t < 64) b1s[t] = lb1[t];
    if (t < 16) b2s[t] = lb2[t];
    if (t < 64) dws[t] = dw[t];
    if (t < 4)  dbs[t] = db[t];
    __syncthreads();

    int lane = t & 31, w = t >> 5;
    int c0   = lane * 2;
    int hd   = lane >> 3;
    int n = blockIdx.x * 8 + w;
    if (n >= NN) return;

    float x0, x1;                       // this lane's 2 channels of GAT-3 output
    agg_node(n, c0, hd, layer, bias, x0, x1);

    // Linear(64,64) + ReLU: need the whole row -> stage via smem
    t1s[w][c0]     = x0;
    t1s[w][c0 + 1] = x1;
    __syncwarp();
    float a0 = b1s[c0], a1 = b1s[c0 + 1];
    #pragma unroll
    for (int k = 0; k < 64; k += 4) {
        float4 xv = *(const float4*)(&t1s[w][k]);
        float2 w0 = *(const float2*)(W1s + (k + 0) * 64 + c0);
        float2 w1 = *(const float2*)(W1s + (k + 1) * 64 + c0);
        float2 w2 = *(const float2*)(W1s + (k + 2) * 64 + c0);
        float2 w3 = *(const float2*)(W1s + (k + 3) * 64 + c0);
        a0 += xv.x * w0.x; a1 += xv.x * w0.y;
        a0 += xv.y * w1.x; a1 += xv.y * w1.y;
        a0 += xv.z * w2.x; a1 += xv.z * w2.y;
        a0 += xv.w * w3.x; a1 += xv.w * w3.y;
    }
    a0 = a0 > 0.f ? a0 : 0.f;
    a1 = a1 > 0.f ? a1 : 0.f;
    __syncwarp();
    t1s[w][c0]     = a0;
    t1s[w][c0 + 1] = a1;
    __syncwarp();
    if (lane < 16) {
        float acc = b2s[lane];
        #pragma unroll
        for (int k = 0; k < 64; k++) acc += t1s[w][k] * W2s[k * 16 + lane];
        t2s[w][lane] = acc;
    }
    __syncwarp();
    if (lane < 4) {
        float lg = dbs[lane];
        #pragma unroll
        for (int i = 0; i < 16; i++) lg += t2s[w][i] * dws[i * 4 + lane];
        lgs[w][lane] = lg;
    }
    __syncwarp();
    if (lane < 4) {
        float l0 = lgs[w][0], l1 = lgs[w][1], l2 = lgs[w][2], l3 = lgs[w][3];
        float mx = fmaxf(fmaxf(l0, l1), fmaxf(l2, l3));
        float e0 = __expf(l0 - mx), e1 = __expf(l1 - mx);
        float e2 = __expf(l2 - mx), e3 = __expf(l3 - mx);
        float den = e0 + e1 + e2 + e3;
        float mine = (lane == 0) ? e0 : (lane == 1) ? e1 : (lane == 2) ? e2 : e3;
        out[(size_t)n * 4 + lane] = mine / den;
    }
}

// ------------------------------------------------------------------
extern "C" void kernel_launch(void* const* d_in, const int* in_sizes, int n_in,
                              void* d_out, int out_size)
{
    const float* x   = (const float*)d_in[0];
    const int*   ei  = (const int*)  d_in[1];
    int E = in_sizes[1] / 2;
    const int* src = ei;
    const int* dst = ei + E;
    const float* W0  = (const float*)d_in[2];
    const float* as0 = (const float*)d_in[3];
    const float* ad0 = (const float*)d_in[4];
    const float* b0  = (const float*)d_in[5];
    const float* W1  = (const float*)d_in[6];
    const float* as1 = (const float*)d_in[7];
    const float* ad1 = (const float*)d_in[8];
    const float* b1  = (const float*)d_in[9];
    const float* W2  = (const float*)d_in[10];
    const float* as2 = (const float*)d_in[11];
    const float* ad2 = (const float*)d_in[12];
    const float* b2  = (const float*)d_in[13];
    const float* lw1 = (const float*)d_in[14];
    const float* lb1 = (const float*)d_in[15];
    const float* lw2 = (const float*)d_in[16];
    const float* lb2 = (const float*)d_in[17];
    const float* dw  = (const float*)d_in[18];
    const float* db  = (const float*)d_in[19];
    float* out = (float*)d_out;

    const int NODE_BLOCKS = (NN + 7) / 8;   // one warp per node, 8 warps/block
    const int NT = 256;

    // CSR build (reused across all 3 GAT layers)
    k_init_deg<<<(NN + 255) / 256, 256>>>();
    k_hist<<<(E + 255) / 256, 256>>>(dst, E);
    k_scan<<<1, 1024>>>();
    k_fill<<<(E + NN + 255) / 256, 256>>>(src, dst, E);

    // GAT layer 0 (Fin=1): out -> g_fa
    k_transform<<<NODE_BLOCKS, NT>>>(x, 0, 1, W0, as0, ad0);
    k_gmax<<<296, 256>>>(0);
    k_aggregate<<<NODE_BLOCKS, NT>>>(b0, 1, 0);
    // GAT layer 1 (Fin=64): in g_fa, out -> g_fb
    k_transform<<<NODE_BLOCKS, NT>>>(nullptr, 1, 64, W1, as1, ad1);
    k_gmax<<<296, 256>>>(1);
    k_aggregate<<<NODE_BLOCKS, NT>>>(b1, 2, 1);
    // GAT layer 2 (Fin=64): in g_fb, fused aggregate + MLP + decoder -> out
    k_transform<<<NODE_BLOCKS, NT>>>(nullptr, 2, 64, W2, as2, ad2);
    k_gmax<<<296, 256>>>(2);
    k_agg_mlp<<<NODE_BLOCKS, NT>>>(b2, 2, lw1, lb1, lw2, lb2, dw, db, out);
}

// round 4
// speedup vs baseline: 1.2110x; 1.0288x over previous
#include <cuda_runtime.h>

#define NN 100000
#define EMAX 1600000

// ---- scratch (device globals; no runtime allocation allowed) ----
__device__ int      g_deg[NN];
__device__ int      g_off[NN + 1];
__device__ int      g_cur[NN];
__device__ int      g_csr[EMAX + NN];   // src node per CSR slot (sorted by dst)
__device__ float    g_h [NN * 64];      // transformed features for current layer
__device__ float    g_fa[NN * 64];      // ping
__device__ float    g_fb[NN * 64];      // pong
__device__ float    g_es[NN * 4];       // per-node source attention logits
__device__ float    g_ed[NN * 4];       // per-node dest attention logits
__device__ unsigned g_gmax[12];         // per-layer per-head global max of es (ordered-uint)

// ordered-uint encoding for float atomicMax
__device__ __forceinline__ unsigned fenc(float f) {
    unsigned u = __float_as_uint(f);
    return u ^ ((u & 0x80000000u) ? 0xFFFFFFFFu : 0x80000000u);
}
__device__ __forceinline__ float fdec(unsigned e) {
    unsigned u = e ^ ((e & 0x80000000u) ? 0x80000000u : 0xFFFFFFFFu);
    return __uint_as_float(u);
}
__device__ __forceinline__ float leaky02(float e) {
    return (e > 0.f) ? e : 0.2f * e;
}

// ------------------------------------------------------------------
// CSR construction
// ------------------------------------------------------------------
__global__ void k_init_deg() {
    int i = blockIdx.x * blockDim.x + threadIdx.x;
    if (i < NN) g_deg[i] = 1;           // self-loop
    if (i < 12) g_gmax[i] = 0u;         // -inf (ordered encoding)
}

__global__ void k_hist(const int* __restrict__ dst, int E) {
    int i = blockIdx.x * blockDim.x + threadIdx.x;
    if (i < E) atomicAdd(&g_deg[dst[i]], 1);
}

// single-block exclusive scan over g_deg -> g_off, g_cur
__global__ void k_scan() {
    __shared__ int sums[1024];
    const int CH = (NN + 1023) / 1024;
    int t = threadIdx.x;
    int lo = t * CH;
    int hi = lo + CH; if (hi > NN) hi = NN;
    int s = 0;
    for (int i = lo; i < hi; i++) s += g_deg[i];
    sums[t] = s;
    __syncthreads();
    for (int off = 1; off < 1024; off <<= 1) {
        int v = (t >= off) ? sums[t - off] : 0;
        __syncthreads();
        sums[t] += v;
        __syncthreads();
    }
    int pref = (t == 0) ? 0 : sums[t - 1];
    for (int i = lo; i < hi; i++) {
        g_off[i] = pref;
        g_cur[i] = pref;
        pref += g_deg[i];
    }
    if (t == 1023) g_off[NN] = sums[1023];
}

__global__ void k_fill(const int* __restrict__ src, const int* __restrict__ dst, int E) {
    int i = blockIdx.x * blockDim.x + threadIdx.x;
    int tot = E + NN;
    if (i >= tot) return;
    int s, d;
    if (i < E) { s = src[i]; d = dst[i]; }
    else       { s = i - E; d = s; }    // self-loops
    int p = atomicAdd(&g_cur[d], 1);
    g_csr[p] = s;
}

// ------------------------------------------------------------------
// Node transform: h = xin @ W ; es/ed = attention dots; fused per-head
// global max of es (block smem reduce + global atomic). One warp/node.
// ------------------------------------------------------------------
__global__ __launch_bounds__(256) void k_transform(
    const float* __restrict__ xext, int xin_sel, int Fin,
    const float* __restrict__ Wg,
    const float* __restrict__ avs,
    const float* __restrict__ avd,
    int layer)
{
    __shared__ float Ws[64 * 64];
    __shared__ float As[64], Ad[64];
    __shared__ unsigned bmax[4];
    const float* xin = (xin_sel == 0) ? xext : (xin_sel == 1 ? g_fa : g_fb);
    int t = threadIdx.x;
    for (int i = t; i < Fin * 64; i += blockDim.x) Ws[i] = Wg[i];
    if (t < 64) { As[t] = avs[t]; Ad[t] = avd[t]; }
    if (t < 4)  bmax[t] = 0u;
    __syncthreads();

    int lane = t & 31;
    int c0   = lane * 2;
    int n = blockIdx.x * 8 + (t >> 5);

    if (n < NN) {
        float a0, a1;
        if (Fin == 1) {
            float xv = __ldg(xin + n);
            a0 = xv * Ws[c0];
            a1 = xv * Ws[c0 + 1];
        } else {
            a0 = 0.f; a1 = 0.f;
            const float* xr = xin + (size_t)n * 64;
            #pragma unroll
            for (int k = 0; k < 64; k += 4) {
                float4 xv = __ldg((const float4*)(xr + k));
                float2 w0 = *(const float2*)(Ws + (k + 0) * 64 + c0);
                float2 w1 = *(const float2*)(Ws + (k + 1) * 64 + c0);
                float2 w2 = *(const float2*)(Ws + (k + 2) * 64 + c0);
                float2 w3 = *(const float2*)(Ws + (k + 3) * 64 + c0);
                a0 += xv.x * w0.x; a1 += xv.x * w0.y;
                a0 += xv.y * w1.x; a1 += xv.y * w1.y;
                a0 += xv.z * w2.x; a1 += xv.z * w2.y;
                a0 += xv.w * w3.x; a1 += xv.w * w3.y;
            }
        }
        size_t base = (size_t)n * 64 + c0;
        g_h[base]     = a0;
        g_h[base + 1] = a1;
        float ps = a0 * As[c0] + a1 * As[c0 + 1];
        float pd = a0 * Ad[c0] + a1 * Ad[c0 + 1];
        #pragma unroll
        for (int o = 4; o >= 1; o >>= 1) {
            ps += __shfl_down_sync(0xffffffffu, ps, o);
            pd += __shfl_down_sync(0xffffffffu, pd, o);
        }
        if ((lane & 7) == 0) {
            int hd = lane >> 3;
            g_es[n * 4 + hd] = ps;
            g_ed[n * 4 + hd] = pd;
            atomicMax(&bmax[hd], fenc(ps));
        }
    }
    __syncthreads();
    if (t < 4) atomicMax(&g_gmax[layer * 4 + t], bmax[t]);
}

// ------------------------------------------------------------------
// Single-pass softmax aggregation core (one warp per node).
// Register-staged: per 8-edge chunk, load all csr indices first
// (one latency round), then all dependent es/h loads (second round).
// ------------------------------------------------------------------
__device__ __forceinline__ void agg_node(
    int n, int c0, int hd, int layer, const float* __restrict__ bias,
    float& o0, float& o1)
{
    int beg = __ldg(&g_off[n]), end = __ldg(&g_off[n + 1]);
    float edv = __ldg(&g_ed[n * 4 + hd]);
    float m = leaky02(fdec(g_gmax[layer * 4 + hd]) + edv);  // >= every edge logit

    float s = 0.f, acc0 = 0.f, acc1 = 0.f;
    int p = beg;
    for (; p + 8 <= end; p += 8) {
        int sc[8];
        #pragma unroll
        for (int j = 0; j < 8; j++) sc[j] = __ldg(&g_csr[p + j]);
        float ev[8]; float2 hv[8];
        #pragma unroll
        for (int j = 0; j < 8; j++) {
            ev[j] = __ldg(&g_es[sc[j] * 4 + hd]);
            hv[j] = __ldg((const float2*)(g_h + (size_t)sc[j] * 64 + c0));
        }
        #pragma unroll
        for (int j = 0; j < 8; j++) {
            float w = __expf(leaky02(ev[j] + edv) - m);
            s    += w;
            acc0 += w * hv[j].x;
            acc1 += w * hv[j].y;
        }
    }
    if (p + 4 <= end) {
        int sc[4];
        #pragma unroll
        for (int j = 0; j < 4; j++) sc[j] = __ldg(&g_csr[p + j]);
        float ev[4]; float2 hv[4];
        #pragma unroll
        for (int j = 0; j < 4; j++) {
            ev[j] = __ldg(&g_es[sc[j] * 4 + hd]);
            hv[j] = __ldg((const float2*)(g_h + (size_t)sc[j] * 64 + c0));
        }
        #pragma unroll
        for (int j = 0; j < 4; j++) {
            float w = __expf(leaky02(ev[j] + edv) - m);
            s    += w;
            acc0 += w * hv[j].x;
            acc1 += w * hv[j].y;
        }
        p += 4;
    }
    for (; p < end; p++) {
        int sc = __ldg(&g_csr[p]);
        float  e  = __ldg(&g_es[sc * 4 + hd]);
        float2 hv = __ldg((const float2*)(g_h + (size_t)sc * 64 + c0));
        float w = __expf(leaky02(e + edv) - m);
        s    += w;
        acc0 += w * hv.x;
        acc1 += w * hv.y;
    }
    float inv = 1.f / (s + 1e-16f);
    o0 = acc0 * inv + bias[c0];
    o1 = acc1 * inv + bias[c0 + 1];
}

// ------------------------------------------------------------------
// Aggregation -> feature buffer (layers 0 and 1)
// ------------------------------------------------------------------
__global__ __launch_bounds__(256) void k_aggregate(
    const float* __restrict__ bias, int out_sel, int layer)
{
    float* xout = (out_sel == 1) ? g_fa : g_fb;
    int t    = threadIdx.x;
    int lane = t & 31;
    int c0   = lane * 2;
    int hd   = lane >> 3;
    int n = blockIdx.x * 8 + (t >> 5);
    if (n >= NN) return;
    float o0, o1;
    agg_node(n, c0, hd, layer, bias, o0, o1);
    size_t base = (size_t)n * 64 + c0;
    xout[base]     = o0;
    xout[base + 1] = o1;
}

// ------------------------------------------------------------------
// Aggregation (layer 2) fused with MLP + decoder + softmax epilogue
// ------------------------------------------------------------------
__global__ __launch_bounds__(256) void k_agg_mlp(
    const float* __restrict__ bias, int layer,
    const float* __restrict__ lw1, const float* __restrict__ lb1,
    const float* __restrict__ lw2, const float* __restrict__ lb2,
    const float* __restrict__ dw,  const float* __restrict__ db,
    float* __restrict__ out)
{
    __shared__ float W1s[64 * 64];
    __shared__ float W2s[64 * 16];
    __shared__ float b1s[64], b2s[16], dws[64], dbs[4];
    __shared__ float t1s[8][64];
    __shared__ float t2s[8][16];
    __shared__ float lgs[8][4];
    int t = threadIdx.x;
    for (int i = t; i < 64 * 64; i += blockDim.x) W1s[i] = lw1[i];
    for (int i = t; i < 64 * 16; i += blockDim.x) W2s[i] = lw2[i];
    if (t < 64) b1s[t] = lb1[t];
    if (t < 16) b2s[t] = lb2[t];
    if (t < 64) dws[t] = dw[t];
    if (t < 4)  dbs[t] = db[t];
    __syncthreads();

    int lane = t & 31, w = t >> 5;
    int c0   = lane * 2;
    int hd   = lane >> 3;
    int n = blockIdx.x * 8 + w;
    if (n >= NN) return;

    float x0, x1;
    agg_node(n, c0, hd, layer, bias, x0, x1);

    t1s[w][c0]     = x0;
    t1s[w][c0 + 1] = x1;
    __syncwarp();
    float a0 = b1s[c0], a1 = b1s[c0 + 1];
    #pragma unroll
    for (int k = 0; k < 64; k += 4) {
        float4 xv = *(const float4*)(&t1s[w][k]);
        float2 w0 = *(const float2*)(W1s + (k + 0) * 64 + c0);
        float2 w1 = *(const float2*)(W1s + (k + 1) * 64 + c0);
        float2 w2 = *(const float2*)(W1s + (k + 2) * 64 + c0);
        float2 w3 = *(const float2*)(W1s + (k + 3) * 64 + c0);
        a0 += xv.x * w0.x; a1 += xv.x * w0.y;
        a0 += xv.y * w1.x; a1 += xv.y * w1.y;
        a0 += xv.z * w2.x; a1 += xv.z * w2.y;
        a0 += xv.w * w3.x; a1 += xv.w * w3.y;
    }
    a0 = a0 > 0.f ? a0 : 0.f;
    a1 = a1 > 0.f ? a1 : 0.f;
    __syncwarp();
    t1s[w][c0]     = a0;
    t1s[w][c0 + 1] = a1;
    __syncwarp();
    if (lane < 16) {
        float acc = b2s[lane];
        #pragma unroll
        for (int k = 0; k < 64; k++) acc += t1s[w][k] * W2s[k * 16 + lane];
        t2s[w][lane] = acc;
    }
    __syncwarp();
    if (lane < 4) {
        float lg = dbs[lane];
        #pragma unroll
        for (int i = 0; i < 16; i++) lg += t2s[w][i] * dws[i * 4 + lane];
        lgs[w][lane] = lg;
    }
    __syncwarp();
    if (lane < 4) {
        float l0 = lgs[w][0], l1 = lgs[w][1], l2 = lgs[w][2], l3 = lgs[w][3];
        float mx = fmaxf(fmaxf(l0, l1), fmaxf(l2, l3));
        float e0 = __expf(l0 - mx), e1 = __expf(l1 - mx);
        float e2 = __expf(l2 - mx), e3 = __expf(l3 - mx);
        float den = e0 + e1 + e2 + e3;
        float mine = (lane == 0) ? e0 : (lane == 1) ? e1 : (lane == 2) ? e2 : e3;
        out[(size_t)n * 4 + lane] = mine / den;
    }
}

// ------------------------------------------------------------------
extern "C" void kernel_launch(void* const* d_in, const int* in_sizes, int n_in,
                              void* d_out, int out_size)
{
    const float* x   = (const float*)d_in[0];
    const int*   ei  = (const int*)  d_in[1];
    int E = in_sizes[1] / 2;
    const int* src = ei;
    const int* dst = ei + E;
    const float* W0  = (const float*)d_in[2];
    const float* as0 = (const float*)d_in[3];
    const float* ad0 = (const float*)d_in[4];
    const float* b0  = (const float*)d_in[5];
    const float* W1  = (const float*)d_in[6];
    const float* as1 = (const float*)d_in[7];
    const float* ad1 = (const float*)d_in[8];
    const float* b1  = (const float*)d_in[9];
    const float* W2  = (const float*)d_in[10];
    const float* as2 = (const float*)d_in[11];
    const float* ad2 = (const float*)d_in[12];
    const float* b2  = (const float*)d_in[13];
    const float* lw1 = (const float*)d_in[14];
    const float* lb1 = (const float*)d_in[15];
    const float* lw2 = (const float*)d_in[16];
    const float* lb2 = (const float*)d_in[17];
    const float* dw  = (const float*)d_in[18];
    const float* db  = (const float*)d_in[19];
    float* out = (float*)d_out;

    const int NODE_BLOCKS = (NN + 7) / 8;   // one warp per node, 8 warps/block
    const int NT = 256;

    // CSR build (reused across all 3 GAT layers)
    k_init_deg<<<(NN + 255) / 256, 256>>>();
    k_hist<<<(E + 255) / 256, 256>>>(dst, E);
    k_scan<<<1, 1024>>>();
    k_fill<<<(E + NN + 255) / 256, 256>>>(src, dst, E);

    // GAT layer 0 (Fin=1): out -> g_fa
    k_transform<<<NODE_BLOCKS, NT>>>(x, 0, 1, W0, as0, ad0, 0);
    k_aggregate<<<NODE_BLOCKS, NT>>>(b0, 1, 0);
    // GAT layer 1 (Fin=64): in g_fa, out -> g_fb
    k_transform<<<NODE_BLOCKS, NT>>>(nullptr, 1, 64, W1, as1, ad1, 1);
    k_aggregate<<<NODE_BLOCKS, NT>>>(b1, 2, 1);
    // GAT layer 2 (Fin=64): in g_fb, fused aggregate + MLP + decoder -> out
    k_transform<<<NODE_BLOCKS, NT>>>(nullptr, 2, 64, W2, as2, ad2, 2);
    k_agg_mlp<<<NODE_BLOCKS, NT>>>(b2, 2, lw1, lb1, lw2, lb2, dw, db, out);
}

// round 5
// speedup vs baseline: 1.2346x; 1.0194x over previous
#include <cuda_runtime.h>

#define NN 100000
#define EMAX 1600000

// ---- scratch (device globals; no runtime allocation allowed) ----
__device__ int      g_deg[NN];
__device__ int      g_off[NN + 1];
__device__ int      g_cur[NN];
__device__ int      g_csr[EMAX + NN];   // src node per CSR slot (sorted by dst)
__device__ float    g_h [NN * 64];      // transformed features for current layer
__device__ float    g_fa[NN * 64];      // ping
__device__ float    g_fb[NN * 64];      // pong
__device__ float    g_es[NN * 4];       // per-node source attention logits
__device__ float    g_ed[NN * 4];       // per-node dest attention logits
__device__ unsigned g_gmax[12];         // per-layer per-head global max of es (ordered-uint)

__device__ __forceinline__ unsigned fenc(float f) {
    unsigned u = __float_as_uint(f);
    return u ^ ((u & 0x80000000u) ? 0xFFFFFFFFu : 0x80000000u);
}
__device__ __forceinline__ float fdec(unsigned e) {
    unsigned u = e ^ ((e & 0x80000000u) ? 0x80000000u : 0xFFFFFFFFu);
    return __uint_as_float(u);
}
__device__ __forceinline__ float leaky02(float e) {
    return (e > 0.f) ? e : 0.2f * e;
}

// ------------------------------------------------------------------
// CSR construction
// ------------------------------------------------------------------
__global__ void k_init_deg() {
    int i = blockIdx.x * blockDim.x + threadIdx.x;
    if (i < NN) g_deg[i] = 1;           // self-loop
    if (i < 12) g_gmax[i] = 0u;         // -inf (ordered encoding)
}

__global__ void k_hist(const int* __restrict__ dst, int E) {
    int i = blockIdx.x * blockDim.x + threadIdx.x;
    if (i < E) atomicAdd(&g_deg[dst[i]], 1);
}

__global__ void k_scan() {
    __shared__ int sums[1024];
    const int CH = (NN + 1023) / 1024;
    int t = threadIdx.x;
    int lo = t * CH;
    int hi = lo + CH; if (hi > NN) hi = NN;
    int s = 0;
    for (int i = lo; i < hi; i++) s += g_deg[i];
    sums[t] = s;
    __syncthreads();
    for (int off = 1; off < 1024; off <<= 1) {
        int v = (t >= off) ? sums[t - off] : 0;
        __syncthreads();
        sums[t] += v;
        __syncthreads();
    }
    int pref = (t == 0) ? 0 : sums[t - 1];
    for (int i = lo; i < hi; i++) {
        g_off[i] = pref;
        g_cur[i] = pref;
        pref += g_deg[i];
    }
    if (t == 1023) g_off[NN] = sums[1023];
}

__global__ void k_fill(const int* __restrict__ src, const int* __restrict__ dst, int E) {
    int i = blockIdx.x * blockDim.x + threadIdx.x;
    int tot = E + NN;
    if (i >= tot) return;
    int s, d;
    if (i < E) { s = src[i]; d = dst[i]; }
    else       { s = i - E; d = s; }    // self-loops
    int p = atomicAdd(&g_cur[d], 1);
    g_csr[p] = s;
}

// ------------------------------------------------------------------
// Node transform: 4 nodes per warp (amortize W smem staging).
// h = xin @ W ; es/ed attention dots; fused per-head global max.
// ------------------------------------------------------------------
__global__ __launch_bounds__(256) void k_transform(
    const float* __restrict__ xext, int xin_sel, int Fin,
    const float* __restrict__ Wg,
    const float* __restrict__ avs,
    const float* __restrict__ avd,
    int layer)
{
    __shared__ float Ws[64 * 64];
    __shared__ float As[64], Ad[64];
    __shared__ unsigned bmax[4];
    const float* xin = (xin_sel == 0) ? xext : (xin_sel == 1 ? g_fa : g_fb);
    int t = threadIdx.x;
    for (int i = t; i < Fin * 64; i += blockDim.x) Ws[i] = Wg[i];
    if (t < 64) { As[t] = avs[t]; Ad[t] = avd[t]; }
    if (t < 4)  bmax[t] = 0u;
    __syncthreads();

    int lane = t & 31;
    int c0   = lane * 2;
    int n0 = blockIdx.x * 32 + (t >> 5) * 4;

    #pragma unroll
    for (int r = 0; r < 4; r++) {
        int n = n0 + r;
        if (n >= NN) break;
        float a0, a1;
        if (Fin == 1) {
            float xv = __ldg(xin + n);
            a0 = xv * Ws[c0];
            a1 = xv * Ws[c0 + 1];
        } else {
            a0 = 0.f; a1 = 0.f;
            const float* xr = xin + (size_t)n * 64;
            #pragma unroll
            for (int k = 0; k < 64; k += 4) {
                float4 xv = __ldg((const float4*)(xr + k));
                float2 w0 = *(const float2*)(Ws + (k + 0) * 64 + c0);
                float2 w1 = *(const float2*)(Ws + (k + 1) * 64 + c0);
                float2 w2 = *(const float2*)(Ws + (k + 2) * 64 + c0);
                float2 w3 = *(const float2*)(Ws + (k + 3) * 64 + c0);
                a0 += xv.x * w0.x; a1 += xv.x * w0.y;
                a0 += xv.y * w1.x; a1 += xv.y * w1.y;
                a0 += xv.z * w2.x; a1 += xv.z * w2.y;
                a0 += xv.w * w3.x; a1 += xv.w * w3.y;
            }
        }
        size_t base = (size_t)n * 64 + c0;
        g_h[base]     = a0;
        g_h[base + 1] = a1;
        float ps = a0 * As[c0] + a1 * As[c0 + 1];
        float pd = a0 * Ad[c0] + a1 * Ad[c0 + 1];
        #pragma unroll
        for (int o = 4; o >= 1; o >>= 1) {
            ps += __shfl_down_sync(0xffffffffu, ps, o);
            pd += __shfl_down_sync(0xffffffffu, pd, o);
        }
        if ((lane & 7) == 0) {
            int hd = lane >> 3;
            g_es[n * 4 + hd] = ps;
            g_ed[n * 4 + hd] = pd;
            atomicMax(&bmax[hd], fenc(ps));
        }
    }
    __syncthreads();
    if (t < 4) atomicMax(&g_gmax[layer * 4 + t], bmax[t]);
}

// ------------------------------------------------------------------
// Single-pass softmax aggregation core (one warp per node).
// Coalesced csr load (lane l -> csr[base+l]) + shuffle broadcast:
// removes the index-load level of the dependent chain entirely.
// ------------------------------------------------------------------
__device__ __forceinline__ void agg_node(
    int n, int c0, int hd, int lane, int layer, const float* __restrict__ bias,
    float& o0, float& o1)
{
    int beg = __ldg(&g_off[n]), end = __ldg(&g_off[n + 1]);
    float edv = __ldg(&g_ed[n * 4 + hd]);
    float m = leaky02(fdec(g_gmax[layer * 4 + hd]) + edv);  // >= every edge logit

    float s = 0.f, acc0 = 0.f, acc1 = 0.f;
    for (int base = beg; base < end; base += 32) {
        int rem = end - base;
        int cnt = rem < 32 ? rem : 32;
        int safel = lane < rem ? lane : 0;
        int myidx = __ldg(&g_csr[base + safel]);   // one coalesced load, 32 edges
        int j = 0;
        for (; j + 8 <= cnt; j += 8) {
            int sc[8]; float ev[8]; float2 hv[8];
            #pragma unroll
            for (int q = 0; q < 8; q++)
                sc[q] = __shfl_sync(0xffffffffu, myidx, j + q);
            #pragma unroll
            for (int q = 0; q < 8; q++) {
                ev[q] = __ldg(&g_es[sc[q] * 4 + hd]);
                hv[q] = __ldg((const float2*)(g_h + (size_t)sc[q] * 64 + c0));
            }
            #pragma unroll
            for (int q = 0; q < 8; q++) {
                float w = __expf(leaky02(ev[q] + edv) - m);
                s    += w;
                acc0 += w * hv[q].x;
                acc1 += w * hv[q].y;
            }
        }
        if (j + 4 <= cnt) {
            int sc[4]; float ev[4]; float2 hv[4];
            #pragma unroll
            for (int q = 0; q < 4; q++)
                sc[q] = __shfl_sync(0xffffffffu, myidx, j + q);
            #pragma unroll
            for (int q = 0; q < 4; q++) {
                ev[q] = __ldg(&g_es[sc[q] * 4 + hd]);
                hv[q] = __ldg((const float2*)(g_h + (size_t)sc[q] * 64 + c0));
            }
            #pragma unroll
            for (int q = 0; q < 4; q++) {
                float w = __expf(leaky02(ev[q] + edv) - m);
                s    += w;
                acc0 += w * hv[q].x;
                acc1 += w * hv[q].y;
            }
            j += 4;
        }
        for (; j < cnt; j++) {
            int sc = __shfl_sync(0xffffffffu, myidx, j);
            float  e  = __ldg(&g_es[sc * 4 + hd]);
            float2 hv = __ldg((const float2*)(g_h + (size_t)sc * 64 + c0));
            float w = __expf(leaky02(e + edv) - m);
            s    += w;
            acc0 += w * hv.x;
            acc1 += w * hv.y;
        }
    }
    float inv = 1.f / (s + 1e-16f);
    o0 = acc0 * inv + bias[c0];
    o1 = acc1 * inv + bias[c0 + 1];
}

// ------------------------------------------------------------------
// Aggregation -> feature buffer (layers 0 and 1), one warp per node
// ------------------------------------------------------------------
__global__ __launch_bounds__(256) void k_aggregate(
    const float* __restrict__ bias, int out_sel, int layer)
{
    float* xout = (out_sel == 1) ? g_fa : g_fb;
    int t    = threadIdx.x;
    int lane = t & 31;
    int c0   = lane * 2;
    int hd   = lane >> 3;
    int n = blockIdx.x * 8 + (t >> 5);
    if (n >= NN) return;
    float o0, o1;
    agg_node(n, c0, hd, lane, layer, bias, o0, o1);
    size_t base = (size_t)n * 64 + c0;
    xout[base]     = o0;
    xout[base + 1] = o1;
}

// ------------------------------------------------------------------
// Aggregation (layer 2) fused with MLP + decoder + softmax epilogue.
// 4 nodes per warp (amortize W1/W2 smem staging).
// ------------------------------------------------------------------
__global__ __launch_bounds__(256) void k_agg_mlp(
    const float* __restrict__ bias, int layer,
    const float* __restrict__ lw1, const float* __restrict__ lb1,
    const float* __restrict__ lw2, const float* __restrict__ lb2,
    const float* __restrict__ dw,  const float* __restrict__ db,
    float* __restrict__ out)
{
    __shared__ float W1s[64 * 64];
    __shared__ float W2s[64 * 16];
    __shared__ float b1s[64], b2s[16], dws[64], dbs[4];
    __shared__ float t1s[8][64];
    __shared__ float t2s[8][16];
    __shared__ float lgs[8][4];
    int t = threadIdx.x;
    for (int i = t; i < 64 * 64; i += blockDim.x) W1s[i] = lw1[i];
    for (int i = t; i < 64 * 16; i += blockDim.x) W2s[i] = lw2[i];
    if (t < 64) b1s[t] = lb1[t];
    if (t < 16) b2s[t] = lb2[t];
    if (t < 64) dws[t] = dw[t];
    if (t < 4)  dbs[t] = db[t];
    __syncthreads();

    int lane = t & 31, w = t >> 5;
    int c0   = lane * 2;
    int hd   = lane >> 3;
    int n0 = blockIdx.x * 32 + w * 4;

    #pragma unroll 1
    for (int r = 0; r < 4; r++) {
        int n = n0 + r;
        if (n >= NN) break;

        float x0, x1;
        agg_node(n, c0, hd, lane, layer, bias, x0, x1);

        t1s[w][c0]     = x0;
        t1s[w][c0 + 1] = x1;
        __syncwarp();
        float a0 = b1s[c0], a1 = b1s[c0 + 1];
        #pragma unroll
        for (int k = 0; k < 64; k += 4) {
            float4 xv = *(const float4*)(&t1s[w][k]);
            float2 w0 = *(const float2*)(W1s + (k + 0) * 64 + c0);
            float2 w1 = *(const float2*)(W1s + (k + 1) * 64 + c0);
            float2 w2 = *(const float2*)(W1s + (k + 2) * 64 + c0);
            float2 w3 = *(const float2*)(W1s + (k + 3) * 64 + c0);
            a0 += xv.x * w0.x; a1 += xv.x * w0.y;
            a0 += xv.y * w1.x; a1 += xv.y * w1.y;
            a0 += xv.z * w2.x; a1 += xv.z * w2.y;
            a0 += xv.w * w3.x; a1 += xv.w * w3.y;
        }
        a0 = a0 > 0.f ? a0 : 0.f;
        a1 = a1 > 0.f ? a1 : 0.f;
        __syncwarp();
        t1s[w][c0]     = a0;
        t1s[w][c0 + 1] = a1;
        __syncwarp();
        if (lane < 16) {
            float acc = b2s[lane];
            #pragma unroll
            for (int k = 0; k < 64; k++) acc += t1s[w][k] * W2s[k * 16 + lane];
            t2s[w][lane] = acc;
        }
        __syncwarp();
        if (lane < 4) {
            float lg = dbs[lane];
            #pragma unroll
            for (int i = 0; i < 16; i++) lg += t2s[w][i] * dws[i * 4 + lane];
            lgs[w][lane] = lg;
        }
        __syncwarp();
        if (lane < 4) {
            float l0 = lgs[w][0], l1 = lgs[w][1], l2 = lgs[w][2], l3 = lgs[w][3];
            float mx = fmaxf(fmaxf(l0, l1), fmaxf(l2, l3));
            float e0 = __expf(l0 - mx), e1 = __expf(l1 - mx);
            float e2 = __expf(l2 - mx), e3 = __expf(l3 - mx);
            float den = e0 + e1 + e2 + e3;
            float mine = (lane == 0) ? e0 : (lane == 1) ? e1 : (lane == 2) ? e2 : e3;
            out[(size_t)n * 4 + lane] = mine / den;
        }
        __syncwarp();
    }
}

// ------------------------------------------------------------------
extern "C" void kernel_launch(void* const* d_in, const int* in_sizes, int n_in,
                              void* d_out, int out_size)
{
    const float* x   = (const float*)d_in[0];
    const int*   ei  = (const int*)  d_in[1];
    int E = in_sizes[1] / 2;
    const int* src = ei;
    const int* dst = ei + E;
    const float* W0  = (const float*)d_in[2];
    const float* as0 = (const float*)d_in[3];
    const float* ad0 = (const float*)d_in[4];
    const float* b0  = (const float*)d_in[5];
    const float* W1  = (const float*)d_in[6];
    const float* as1 = (const float*)d_in[7];
    const float* ad1 = (const float*)d_in[8];
    const float* b1  = (const float*)d_in[9];
    const float* W2  = (const float*)d_in[10];
    const float* as2 = (const float*)d_in[11];
    const float* ad2 = (const float*)d_in[12];
    const float* b2  = (const float*)d_in[13];
    const float* lw1 = (const float*)d_in[14];
    const float* lb1 = (const float*)d_in[15];
    const float* lw2 = (const float*)d_in[16];
    const float* lb2 = (const float*)d_in[17];
    const float* dw  = (const float*)d_in[18];
    const float* db  = (const float*)d_in[19];
    float* out = (float*)d_out;

    const int AGG_BLOCKS = (NN + 7) / 8;    // 1 node/warp, 8 warps/block
    const int TRF_BLOCKS = (NN + 31) / 32;  // 4 nodes/warp, 8 warps/block
    const int NT = 256;

    // CSR build (reused across all 3 GAT layers)
    k_init_deg<<<(NN + 255) / 256, 256>>>();
    k_hist<<<(E + 255) / 256, 256>>>(dst, E);
    k_scan<<<1, 1024>>>();
    k_fill<<<(E + NN + 255) / 256, 256>>>(src, dst, E);

    // GAT layer 0 (Fin=1): out -> g_fa
    k_transform<<<TRF_BLOCKS, NT>>>(x, 0, 1, W0, as0, ad0, 0);
    k_aggregate<<<AGG_BLOCKS, NT>>>(b0, 1, 0);
    // GAT layer 1 (Fin=64): in g_fa, out -> g_fb
    k_transform<<<TRF_BLOCKS, NT>>>(nullptr, 1, 64, W1, as1, ad1, 1);
    k_aggregate<<<AGG_BLOCKS, NT>>>(b1, 2, 1);
    // GAT layer 2 (Fin=64): in g_fb, fused aggregate + MLP + decoder -> out
    k_transform<<<TRF_BLOCKS, NT>>>(nullptr, 2, 64, W2, as2, ad2, 2);
    k_agg_mlp<<<TRF_BLOCKS, NT>>>(b2, 2, lw1, lb1, lw2, lb2, dw, db, out);
}

// round 6
// speedup vs baseline: 1.8746x; 1.5184x over previous
#include <cuda_runtime.h>

#define NN 100000
#define EMAX 1600000
#define SCAN_B 1024
#define SCAN_NB ((NN + SCAN_B - 1) / SCAN_B)   // 98

// ---- scratch (device globals; no runtime allocation allowed) ----
__device__ int      g_deg[NN];
__device__ int      g_off[NN + 1];
__device__ int      g_cur[NN];
__device__ int      g_csr[EMAX + NN];   // src node per CSR slot (sorted by dst)
__device__ float    g_h [NN * 64];      // transformed features for current layer
__device__ float    g_fa[NN * 64];      // ping
__device__ float    g_fb[NN * 64];      // pong
__device__ float    g_es[NN * 4];       // per-node source attention logits
__device__ float    g_ed[NN * 4];       // per-node dest attention logits
__device__ unsigned g_gmax[12];         // per-layer per-head global max of es
__device__ int      g_bsum[SCAN_NB];
__device__ int      g_boff[SCAN_NB];

__device__ __forceinline__ unsigned fenc(float f) {
    unsigned u = __float_as_uint(f);
    return u ^ ((u & 0x80000000u) ? 0xFFFFFFFFu : 0x80000000u);
}
__device__ __forceinline__ float fdec(unsigned e) {
    unsigned u = e ^ ((e & 0x80000000u) ? 0x80000000u : 0xFFFFFFFFu);
    return __uint_as_float(u);
}
__device__ __forceinline__ float leaky02(float e) {
    return (e > 0.f) ? e : 0.2f * e;
}

// ------------------------------------------------------------------
// CSR construction
// ------------------------------------------------------------------
__global__ void k_init_deg() {
    int i = blockIdx.x * blockDim.x + threadIdx.x;
    if (i < NN) g_deg[i] = 1;           // self-loop
    if (i < 12) g_gmax[i] = 0u;         // -inf (ordered encoding)
}

__global__ void k_hist(const int* __restrict__ dst, int E) {
    int i = blockIdx.x * blockDim.x + threadIdx.x;
    if (i < E) atomicAdd(&g_deg[dst[i]], 1);
}

// -------- parallel 3-phase scan --------
__global__ void k_scan1() {            // per-1024-chunk reduce (256 thr, 4 elems each)
    __shared__ int red[8];
    int b = blockIdx.x, t = threadIdx.x;
    int s = 0;
    #pragma unroll
    for (int j = 0; j < 4; j++) {
        int idx = b * SCAN_B + j * 256 + t;
        if (idx < NN) s += g_deg[idx];
    }
    #pragma unroll
    for (int o = 16; o >= 1; o >>= 1) s += __shfl_down_sync(0xffffffffu, s, o);
    if ((t & 31) == 0) red[t >> 5] = s;
    __syncthreads();
    if (t == 0) {
        int tot = 0;
        #pragma unroll
        for (int w = 0; w < 8; w++) tot += red[w];
        g_bsum[b] = tot;
    }
}

__global__ void k_scan2() {            // scan the 98 block sums (1 block, 128 thr)
    __shared__ int sh[128];
    int t = threadIdx.x;
    sh[t] = (t < SCAN_NB) ? g_bsum[t] : 0;
    __syncthreads();
    for (int o = 1; o < 128; o <<= 1) {
        int v = (t >= o) ? sh[t - o] : 0;
        __syncthreads();
        sh[t] += v;
        __syncthreads();
    }
    if (t < SCAN_NB) g_boff[t] = (t == 0) ? 0 : sh[t - 1];
    if (t == SCAN_NB - 1) g_off[NN] = sh[t];
}

__global__ void k_scan3() {            // local scan + global offset, coalesced writes
    __shared__ int sh[SCAN_B];
    int b = blockIdx.x, t = threadIdx.x;
    int i = b * SCAN_B + t;
    int v = (i < NN) ? g_deg[i] : 0;
    sh[t] = v;
    __syncthreads();
    for (int o = 1; o < SCAN_B; o <<= 1) {
        int u = (t >= o) ? sh[t - o] : 0;
        __syncthreads();
        sh[t] += u;
        __syncthreads();
    }
    if (i < NN) {
        int ex = sh[t] - v + g_boff[b];
        g_off[i] = ex;
        g_cur[i] = ex;
    }
}

__global__ void k_fill(const int* __restrict__ src, const int* __restrict__ dst, int E) {
    int i = blockIdx.x * blockDim.x + threadIdx.x;
    int tot = E + NN;
    if (i >= tot) return;
    int s, d;
    if (i < E) { s = src[i]; d = dst[i]; }
    else       { s = i - E; d = s; }    // self-loops
    int p = atomicAdd(&g_cur[d], 1);
    g_csr[p] = s;
}

// ------------------------------------------------------------------
// Node transform: 4 nodes per warp, W smem loads hoisted out of the
// node loop (1 LDS per chunk shared by 4 nodes instead of 4).
// ------------------------------------------------------------------
__global__ __launch_bounds__(256) void k_transform(
    const float* __restrict__ xext, int xin_sel, int Fin,
    const float* __restrict__ Wg,
    const float* __restrict__ avs,
    const float* __restrict__ avd,
    int layer)
{
    __shared__ float Ws[64 * 64];
    __shared__ float As[64], Ad[64];
    __shared__ unsigned bmax[4];
    const float* xin = (xin_sel == 0) ? xext : (xin_sel == 1 ? g_fa : g_fb);
    int t = threadIdx.x;
    for (int i = t; i < Fin * 64; i += blockDim.x) Ws[i] = Wg[i];
    if (t < 64) { As[t] = avs[t]; Ad[t] = avd[t]; }
    if (t < 4)  bmax[t] = 0u;
    __syncthreads();

    int lane = t & 31;
    int c0   = lane * 2;
    int n0 = blockIdx.x * 32 + (t >> 5) * 4;
    int nv = NN - n0; if (nv > 4) nv = 4;   // valid nodes this warp (>=1 always)

    float acc[4][2];
    #pragma unroll
    for (int r = 0; r < 4; r++) { acc[r][0] = 0.f; acc[r][1] = 0.f; }

    if (Fin == 1) {
        #pragma unroll
        for (int r = 0; r < 4; r++) {
            if (r < nv) {
                float xv = __ldg(xin + n0 + r);
                acc[r][0] = xv * Ws[c0];
                acc[r][1] = xv * Ws[c0 + 1];
            }
        }
    } else {
        const float* x0p = xin + (size_t)n0 * 64;
        #pragma unroll
        for (int k = 0; k < 64; k += 4) {
            float2 w0 = *(const float2*)(Ws + (k + 0) * 64 + c0);
            float2 w1 = *(const float2*)(Ws + (k + 1) * 64 + c0);
            float2 w2 = *(const float2*)(Ws + (k + 2) * 64 + c0);
            float2 w3 = *(const float2*)(Ws + (k + 3) * 64 + c0);
            #pragma unroll
            for (int r = 0; r < 4; r++) {
                if (r < nv) {
                    float4 xv = __ldg((const float4*)(x0p + r * 64 + k));
                    acc[r][0] += xv.x * w0.x; acc[r][1] += xv.x * w0.y;
                    acc[r][0] += xv.y * w1.x; acc[r][1] += xv.y * w1.y;
                    acc[r][0] += xv.z * w2.x; acc[r][1] += xv.z * w2.y;
                    acc[r][0] += xv.w * w3.x; acc[r][1] += xv.w * w3.y;
                }
            }
        }
    }

    #pragma unroll
    for (int r = 0; r < 4; r++) {
        if (r >= nv) break;
        int n = n0 + r;
        float a0 = acc[r][0], a1 = acc[r][1];
        size_t base = (size_t)n * 64 + c0;
        g_h[base]     = a0;
        g_h[base + 1] = a1;
        float ps = a0 * As[c0] + a1 * As[c0 + 1];
        float pd = a0 * Ad[c0] + a1 * Ad[c0 + 1];
        #pragma unroll
        for (int o = 4; o >= 1; o >>= 1) {
            ps += __shfl_down_sync(0xffffffffu, ps, o);
            pd += __shfl_down_sync(0xffffffffu, pd, o);
        }
        if ((lane & 7) == 0) {
            int hd = lane >> 3;
            g_es[n * 4 + hd] = ps;
            g_ed[n * 4 + hd] = pd;
            atomicMax(&bmax[hd], fenc(ps));
        }
    }
    __syncthreads();
    if (t < 4) atomicMax(&g_gmax[layer * 4 + t], bmax[t]);
}

// ------------------------------------------------------------------
// Single-pass softmax aggregation core (one warp per node).
// Coalesced csr load + shuffle broadcast; register-staged gathers.
// ------------------------------------------------------------------
__device__ __forceinline__ void agg_node(
    int n, int c0, int hd, int lane, int layer, const float* __restrict__ bias,
    float& o0, float& o1)
{
    int beg = __ldg(&g_off[n]), end = __ldg(&g_off[n + 1]);
    float edv = __ldg(&g_ed[n * 4 + hd]);
    float m = leaky02(fdec(g_gmax[layer * 4 + hd]) + edv);  // >= every edge logit

    float s = 0.f, acc0 = 0.f, acc1 = 0.f;
    for (int base = beg; base < end; base += 32) {
        int rem = end - base;
        int cnt = rem < 32 ? rem : 32;
        int safel = lane < rem ? lane : 0;
        int myidx = __ldg(&g_csr[base + safel]);   // one coalesced load, 32 edges
        int j = 0;
        for (; j + 8 <= cnt; j += 8) {
            int sc[8]; float ev[8]; float2 hv[8];
            #pragma unroll
            for (int q = 0; q < 8; q++)
                sc[q] = __shfl_sync(0xffffffffu, myidx, j + q);
            #pragma unroll
            for (int q = 0; q < 8; q++) {
                ev[q] = __ldg(&g_es[sc[q] * 4 + hd]);
                hv[q] = __ldg((const float2*)(g_h + (size_t)sc[q] * 64 + c0));
            }
            #pragma unroll
            for (int q = 0; q < 8; q++) {
                float w = __expf(leaky02(ev[q] + edv) - m);
                s    += w;
                acc0 += w * hv[q].x;
                acc1 += w * hv[q].y;
            }
        }
        if (j + 4 <= cnt) {
            int sc[4]; float ev[4]; float2 hv[4];
            #pragma unroll
            for (int q = 0; q < 4; q++)
                sc[q] = __shfl_sync(0xffffffffu, myidx, j + q);
            #pragma unroll
            for (int q = 0; q < 4; q++) {
                ev[q] = __ldg(&g_es[sc[q] * 4 + hd]);
                hv[q] = __ldg((const float2*)(g_h + (size_t)sc[q] * 64 + c0));
            }
            #pragma unroll
            for (int q = 0; q < 4; q++) {
                float w = __expf(leaky02(ev[q] + edv) - m);
                s    += w;
                acc0 += w * hv[q].x;
                acc1 += w * hv[q].y;
            }
            j += 4;
        }
        for (; j < cnt; j++) {
            int sc = __shfl_sync(0xffffffffu, myidx, j);
            float  e  = __ldg(&g_es[sc * 4 + hd]);
            float2 hv = __ldg((const float2*)(g_h + (size_t)sc * 64 + c0));
            float w = __expf(leaky02(e + edv) - m);
            s    += w;
            acc0 += w * hv.x;
            acc1 += w * hv.y;
        }
    }
    float inv = 1.f / (s + 1e-16f);
    o0 = acc0 * inv + bias[c0];
    o1 = acc1 * inv + bias[c0 + 1];
}

// ------------------------------------------------------------------
// Aggregation -> feature buffer (layers 0 and 1), one warp per node
// ------------------------------------------------------------------
__global__ __launch_bounds__(256) void k_aggregate(
    const float* __restrict__ bias, int out_sel, int layer)
{
    float* xout = (out_sel == 1) ? g_fa : g_fb;
    int t    = threadIdx.x;
    int lane = t & 31;
    int c0   = lane * 2;
    int hd   = lane >> 3;
    int n = blockIdx.x * 8 + (t >> 5);
    if (n >= NN) return;
    float o0, o1;
    agg_node(n, c0, hd, lane, layer, bias, o0, o1);
    size_t base = (size_t)n * 64 + c0;
    xout[base]     = o0;
    xout[base + 1] = o1;
}

// ------------------------------------------------------------------
// Aggregation (layer 2) fused with MLP + decoder + softmax epilogue.
// 4 nodes per warp (amortize W1/W2 smem staging).
// ------------------------------------------------------------------
__global__ __launch_bounds__(256) void k_agg_mlp(
    const float* __restrict__ bias, int layer,
    const float* __restrict__ lw1, const float* __restrict__ lb1,
    const float* __restrict__ lw2, const float* __restrict__ lb2,
    const float* __restrict__ dw,  const float* __restrict__ db,
    float* __restrict__ out)
{
    __shared__ float W1s[64 * 64];
    __shared__ float W2s[64 * 16];
    __shared__ float b1s[64], b2s[16], dws[64], dbs[4];
    __shared__ float t1s[8][64];
    __shared__ float t2s[8][16];
    __shared__ float lgs[8][4];
    int t = threadIdx.x;
    for (int i = t; i < 64 * 64; i += blockDim.x) W1s[i] = lw1[i];
    for (int i = t; i < 64 * 16; i += blockDim.x) W2s[i] = lw2[i];
    if (t < 64) b1s[t] = lb1[t];
    if (t < 16) b2s[t] = lb2[t];
    if (t < 64) dws[t] = dw[t];
    if (t < 4)  dbs[t] = db[t];
    __syncthreads();

    int lane = t & 31, w = t >> 5;
    int c0   = lane * 2;
    int hd   = lane >> 3;
    int n0 = blockIdx.x * 32 + w * 4;

    #pragma unroll 1
    for (int r = 0; r < 4; r++) {
        int n = n0 + r;
        if (n >= NN) break;

        float x0, x1;
        agg_node(n, c0, hd, lane, layer, bias, x0, x1);

        t1s[w][c0]     = x0;
        t1s[w][c0 + 1] = x1;
        __syncwarp();
        float a0 = b1s[c0], a1 = b1s[c0 + 1];
        #pragma unroll
        for (int k = 0; k < 64; k += 4) {
            float4 xv = *(const float4*)(&t1s[w][k]);
            float2 w0 = *(const float2*)(W1s + (k + 0) * 64 + c0);
            float2 w1 = *(const float2*)(W1s + (k + 1) * 64 + c0);
            float2 w2 = *(const float2*)(W1s + (k + 2) * 64 + c0);
            float2 w3 = *(const float2*)(W1s + (k + 3) * 64 + c0);
            a0 += xv.x * w0.x; a1 += xv.x * w0.y;
            a0 += xv.y * w1.x; a1 += xv.y * w1.y;
            a0 += xv.z * w2.x; a1 += xv.z * w2.y;
            a0 += xv.w * w3.x; a1 += xv.w * w3.y;
        }
        a0 = a0 > 0.f ? a0 : 0.f;
        a1 = a1 > 0.f ? a1 : 0.f;
        __syncwarp();
        t1s[w][c0]     = a0;
        t1s[w][c0 + 1] = a1;
        __syncwarp();
        if (lane < 16) {
            float acc = b2s[lane];
            #pragma unroll
            for (int k = 0; k < 64; k++) acc += t1s[w][k] * W2s[k * 16 + lane];
            t2s[w][lane] = acc;
        }
        __syncwarp();
        if (lane < 4) {
            float lg = dbs[lane];
            #pragma unroll
            for (int i = 0; i < 16; i++) lg += t2s[w][i] * dws[i * 4 + lane];
            lgs[w][lane] = lg;
        }
        __syncwarp();
        if (lane < 4) {
            float l0 = lgs[w][0], l1 = lgs[w][1], l2 = lgs[w][2], l3 = lgs[w][3];
            float mx = fmaxf(fmaxf(l0, l1), fmaxf(l2, l3));
            float e0 = __expf(l0 - mx), e1 = __expf(l1 - mx);
            float e2 = __expf(l2 - mx), e3 = __expf(l3 - mx);
            float den = e0 + e1 + e2 + e3;
            float mine = (lane == 0) ? e0 : (lane == 1) ? e1 : (lane == 2) ? e2 : e3;
            out[(size_t)n * 4 + lane] = mine / den;
        }
        __syncwarp();
    }
}

// ------------------------------------------------------------------
extern "C" void kernel_launch(void* const* d_in, const int* in_sizes, int n_in,
                              void* d_out, int out_size)
{
    const float* x   = (const float*)d_in[0];
    const int*   ei  = (const int*)  d_in[1];
    int E = in_sizes[1] / 2;
    const int* src = ei;
    const int* dst = ei + E;
    const float* W0  = (const float*)d_in[2];
    const float* as0 = (const float*)d_in[3];
    const float* ad0 = (const float*)d_in[4];
    const float* b0  = (const float*)d_in[5];
    const float* W1  = (const float*)d_in[6];
    const float* as1 = (const float*)d_in[7];
    const float* ad1 = (const float*)d_in[8];
    const float* b1  = (const float*)d_in[9];
    const float* W2  = (const float*)d_in[10];
    const float* as2 = (const float*)d_in[11];
    const float* ad2 = (const float*)d_in[12];
    const float* b2  = (const float*)d_in[13];
    const float* lw1 = (const float*)d_in[14];
    const float* lb1 = (const float*)d_in[15];
    const float* lw2 = (const float*)d_in[16];
    const float* lb2 = (const float*)d_in[17];
    const float* dw  = (const float*)d_in[18];
    const float* db  = (const float*)d_in[19];
    float* out = (float*)d_out;

    const int AGG_BLOCKS = (NN + 7) / 8;    // 1 node/warp, 8 warps/block
    const int TRF_BLOCKS = (NN + 31) / 32;  // 4 nodes/warp, 8 warps/block
    const int NT = 256;

    // CSR build (reused across all 3 GAT layers)
    k_init_deg<<<(NN + 255) / 256, 256>>>();
    k_hist<<<(E + 255) / 256, 256>>>(dst, E);
    k_scan1<<<SCAN_NB, 256>>>();
    k_scan2<<<1, 128>>>();
    k_scan3<<<SCAN_NB, SCAN_B>>>();
    k_fill<<<(E + NN + 255) / 256, 256>>>(src, dst, E);

    // GAT layer 0 (Fin=1): out -> g_fa
    k_transform<<<TRF_BLOCKS, NT>>>(x, 0, 1, W0, as0, ad0, 0);
    k_aggregate<<<AGG_BLOCKS, NT>>>(b0, 1, 0);
    // GAT layer 1 (Fin=64): in g_fa, out -> g_fb
    k_transform<<<TRF_BLOCKS, NT>>>(nullptr, 1, 64, W1, as1, ad1, 1);
    k_aggregate<<<AGG_BLOCKS, NT>>>(b1, 2, 1);
    // GAT layer 2 (Fin=64): in g_fb, fused aggregate + MLP + decoder -> out
    k_transform<<<TRF_BLOCKS, NT>>>(nullptr, 2, 64, W2, as2, ad2, 2);
    k_agg_mlp<<<TRF_BLOCKS, NT>>>(b2, 2, lw1, lb1, lw2, lb2, dw, db, out);
}